// round 5
// baseline (speedup 1.0000x reference)
#include <cuda_runtime.h>
#include <cuda_bf16.h>
#include <cstdint>

#define NB 16384
#define NV 1024
#define NH 1024
#define NC 64
#define NSTEPS 25

// ---------------------------------------------------------------------------
// Scratch (static __device__ allocations; no cudaMalloc anywhere)
// ---------------------------------------------------------------------------
__device__ float g_bmod[NB * NV];               // 64 MB
__device__ float g_cmod[NB * NH];               // 64 MB
__device__ int8_t g_v[NB * NV];                 // 16 MB (current v, 0/1)
__device__ int8_t g_h[NB * NH];                 // 16 MB
__device__ int8_t g_vd[NB * NV];                // 16 MB (v_data as s8)
__device__ int8_t g_Whi[NV * NH];               // W fixed-point hi plane [V][H]
__device__ int8_t g_Wlo[NV * NH];               // W fixed-point lo plane
__device__ int8_t g_WThi[NH * NV];              // W^T planes [H][V]
__device__ int8_t g_WTlo[NH * NV];
__device__ unsigned g_wmax_bits;
__device__ float g_inv_scale;
__device__ float g_fe_d[NB];
__device__ float g_fe_m[NB];
__device__ float g_fep_d[NB * 16];              // per-(row, 64-col block) softplus partials
__device__ float g_fep_m[NB * 16];

// ---------------------------------------------------------------------------
// threefry2x32 (exact JAX semantics, jax_threefry_partitionable)
// ---------------------------------------------------------------------------
__host__ __device__ __forceinline__ void threefry(uint32_t k0, uint32_t k1,
                                                  uint32_t x0, uint32_t x1,
                                                  uint32_t& o0, uint32_t& o1)
{
    uint32_t ks2 = k0 ^ k1 ^ 0x1BD11BDAu;
#define TF_ROT(x, r) (((x) << (r)) | ((x) >> (32 - (r))))
#define TF_RND(r) { x0 += x1; x1 = TF_ROT(x1, r); x1 ^= x0; }
    x0 += k0; x1 += k1;
    TF_RND(13) TF_RND(15) TF_RND(26) TF_RND(6)
    x0 += k1; x1 += ks2 + 1u;
    TF_RND(17) TF_RND(29) TF_RND(16) TF_RND(24)
    x0 += ks2; x1 += k0 + 2u;
    TF_RND(13) TF_RND(15) TF_RND(26) TF_RND(6)
    x0 += k0; x1 += k1 + 3u;
    TF_RND(17) TF_RND(29) TF_RND(16) TF_RND(24)
    x0 += k1; x1 += ks2 + 4u;
    TF_RND(13) TF_RND(15) TF_RND(26) TF_RND(6)
    x0 += ks2; x1 += k0 + 5u;
    o0 = x0; o1 = x1;
#undef TF_RND
#undef TF_ROT
}

__device__ __forceinline__ float urand(uint32_t k0, uint32_t k1, uint32_t idx)
{
    uint32_t a, b;
    threefry(k0, k1, 0u, idx, a, b);
    uint32_t bits = a ^ b;
    return __uint_as_float((bits >> 9) | 0x3F800000u) - 1.0f;
}

// ---------------------------------------------------------------------------
// MMA / ldmatrix / cp.async helpers (baseline PTX, legal on plain sm_103)
// ---------------------------------------------------------------------------
__device__ __forceinline__ uint32_t smem_u32(const void* p) {
    uint32_t a;
    asm("{ .reg .u64 t; cvta.to.shared.u64 t, %1; cvt.u32.u64 %0, t; }" : "=r"(a) : "l"(p));
    return a;
}
__device__ __forceinline__ void ldsm4(uint32_t* r, uint32_t addr) {
    asm volatile("ldmatrix.sync.aligned.m8n8.x4.shared.b16 {%0,%1,%2,%3}, [%4];"
                 : "=r"(r[0]), "=r"(r[1]), "=r"(r[2]), "=r"(r[3]) : "r"(addr));
}
__device__ __forceinline__ void imma16832(int* d, const uint32_t* a, uint32_t b0, uint32_t b1) {
    asm volatile("mma.sync.aligned.m16n8k32.row.col.s32.s8.s8.s32 "
                 "{%0,%1,%2,%3}, {%4,%5,%6,%7}, {%8,%9}, {%0,%1,%2,%3};"
                 : "+r"(d[0]), "+r"(d[1]), "+r"(d[2]), "+r"(d[3])
                 : "r"(a[0]), "r"(a[1]), "r"(a[2]), "r"(a[3]), "r"(b0), "r"(b1));
}
#define CP_ASYNC16(dst, src) \
    asm volatile("cp.async.cg.shared.global [%0], [%1], 16;" :: "r"(dst), "l"(src))
#define CP_COMMIT() asm volatile("cp.async.commit_group;")
#define CP_WAIT2()  asm volatile("cp.async.wait_group 2;")
#define CP_WAIT1()  asm volatile("cp.async.wait_group 1;")
#define CP_WAIT0()  asm volatile("cp.async.wait_group 0;")

// 64B-row swizzle: chunk c (16B units, 0..3) XORed with (row + row/4) — keeps
// both cp.async stores and ldmatrix phases (8 consecutive rows) conflict-free.
__device__ __forceinline__ uint32_t sw8(int row, int c) {
    return (uint32_t)(row * 64 + (((c ^ (row + (row >> 2))) & 3) << 4));
}

// ---------------------------------------------------------------------------
// W quantization: 16-bit fixed point -> hi/lo s8 planes, both orientations
// ---------------------------------------------------------------------------
__global__ void wmax_reset_kernel() { g_wmax_bits = 0u; }

__global__ void wmax_kernel(const float* __restrict__ W)
{
    int i = blockIdx.x * 1024 + threadIdx.x * 4;
    float m = 0.0f;
    #pragma unroll
    for (int q = 0; q < 4; q++) m = fmaxf(m, fabsf(W[i + q]));
    #pragma unroll
    for (int off = 16; off; off >>= 1)
        m = fmaxf(m, __shfl_down_sync(0xffffffffu, m, off));
    if ((threadIdx.x & 31) == 0)
        atomicMax(&g_wmax_bits, __float_as_uint(m));
}

__global__ void quant_kernel(const float* __restrict__ W)
{
    __shared__ int8_t thi[32][33], tlo[32][33];
    const float S = 32512.0f / __uint_as_float(g_wmax_bits);
    int bx = blockIdx.x * 32;   // h
    int by = blockIdx.y * 32;   // v
    int tx = threadIdx.x, ty = threadIdx.y;  // 32 x 8
    #pragma unroll
    for (int i = 0; i < 32; i += 8) {
        float w = W[(size_t)(by + ty + i) * NH + bx + tx];
        int q = (int)lrintf(w * S);
        int hi = (q + 128) >> 8;            // floor((q+128)/256)
        int lo = q - (hi << 8);             // in [-128, 127]
        size_t o = (size_t)(by + ty + i) * NH + bx + tx;
        g_Whi[o] = (int8_t)hi; g_Wlo[o] = (int8_t)lo;
        thi[ty + i][tx] = (int8_t)hi; tlo[ty + i][tx] = (int8_t)lo;
    }
    __syncthreads();
    #pragma unroll
    for (int i = 0; i < 32; i += 8) {
        size_t o = (size_t)(bx + ty + i) * NV + by + tx;
        g_WThi[o] = thi[tx][ty + i]; g_WTlo[o] = tlo[tx][ty + i];
    }
    if (blockIdx.x == 0 && blockIdx.y == 0 && tx == 0 && ty == 0)
        g_inv_scale = 1.0f / S;
}

// ---------------------------------------------------------------------------
// Conditioning MLP -> b_mod, c_mod
// ---------------------------------------------------------------------------
#define PROWS 8
__global__ void params_kernel(const float* __restrict__ cond, const float* __restrict__ b,
                              const float* __restrict__ c, const float* __restrict__ W1,
                              const float* __restrict__ b1, const float* __restrict__ W2,
                              const float* __restrict__ b2)
{
    __shared__ float sc[PROWS][NC];
    __shared__ float st[PROWS][NC];
    int row0 = blockIdx.x * PROWS;
    int tid = threadIdx.x;  // 256

    for (int i = tid; i < PROWS * NC; i += 256)
        sc[i / NC][i % NC] = cond[(size_t)(row0 + i / NC) * NC + (i % NC)];
    __syncthreads();
    for (int i = tid; i < PROWS * NC; i += 256) {
        int r = i / NC, j = i % NC;
        float s = b1[j];
        #pragma unroll 8
        for (int k = 0; k < NC; k++) s += sc[r][k] * W1[k * NC + j];
        st[r][j] = tanhf(s);
    }
    __syncthreads();

    for (int q = tid; q < NV; q += 256) {
        float ga[PROWS], be[PROWS];
        float ig = b2[q], ib = b2[NV + q];
        #pragma unroll
        for (int r = 0; r < PROWS; r++) { ga[r] = ig; be[r] = ib; }
        for (int k = 0; k < NC; k++) {
            float wg = W2[(size_t)k * 4096 + q];
            float wb = W2[(size_t)k * 4096 + NV + q];
            #pragma unroll
            for (int r = 0; r < PROWS; r++) { ga[r] += st[r][k] * wg; be[r] += st[r][k] * wb; }
        }
        float bq = b[q];
        #pragma unroll
        for (int r = 0; r < PROWS; r++)
            g_bmod[(size_t)(row0 + r) * NV + q] = (1.0f + ga[r]) * bq + be[r];
    }
    for (int q = tid; q < NH; q += 256) {
        float ga[PROWS], be[PROWS];
        float ig = b2[2 * NV + q], ib = b2[2 * NV + NH + q];
        #pragma unroll
        for (int r = 0; r < PROWS; r++) { ga[r] = ig; be[r] = ib; }
        for (int k = 0; k < NC; k++) {
            float wg = W2[(size_t)k * 4096 + 2 * NV + q];
            float wb = W2[(size_t)k * 4096 + 2 * NV + NH + q];
            #pragma unroll
            for (int r = 0; r < PROWS; r++) { ga[r] += st[r][k] * wg; be[r] += st[r][k] * wb; }
        }
        float cq = c[q];
        #pragma unroll
        for (int r = 0; r < PROWS; r++)
            g_cmod[(size_t)(row0 + r) * NH + q] = (1.0f + ga[r]) * cq + be[r];
    }
}

// ---------------------------------------------------------------------------
// v_start = bernoulli(k_start, 0.5) as s8; v_data -> s8
// ---------------------------------------------------------------------------
__global__ void init_v_kernel(uint32_t k0, uint32_t k1)
{
    uint32_t i = blockIdx.x * blockDim.x + threadIdx.x;
    float u = urand(k0, k1, i);
    g_v[i] = (u < 0.5f) ? 1 : 0;
}
__global__ void conv_vdata_kernel(const float* __restrict__ vd)
{
    uint32_t i = blockIdx.x * blockDim.x + threadIdx.x;
    g_vd[i] = (int8_t)vd[i];
}

// ---------------------------------------------------------------------------
// int8 fused GEMM: z_int[128x128] = 256*(A@BH^T) + (A@BL^T);  z = z_int/S + bias
//   MODE 0: Out = bernoulli(sigmoid(z))  (s8 0/1)
//   MODE 1: fe_part[row*16 + bx*2 + half] = sum_{64 cols} softplus(z)
// 4-stage cp.async pipeline, K-chunk 64 (2 x k32 mma), warps 2(M)x4(N).
// ---------------------------------------------------------------------------
#define NKIT 16                  // 1024 / 64
#define STAGE_BYTES 24576        // A(8K) + BH(8K) + BL(8K), int8
#define NSTAGE 4
#define SMEM_TOTAL (NSTAGE * STAGE_BYTES)   // 96 KB

__device__ __forceinline__ void stage_load(uint32_t s_stage,
    const int8_t* A, const int8_t* BH, const int8_t* BL,
    int m0, int n0, int kk, int tid)
{
    #pragma unroll
    for (int r = 0; r < 6; r++) {
        int i = tid + r * 256;          // 0..1535
        int buf = i >> 9;               // 0:A 1:BH 2:BL
        int row = (i >> 2) & 127;
        int ch  = i & 3;
        const char* src;
        if (buf == 0)      src = (const char*)A  + (size_t)(m0 + row) * 1024 + kk * 64 + ch * 16;
        else if (buf == 1) src = (const char*)BH + (size_t)(n0 + row) * 1024 + kk * 64 + ch * 16;
        else               src = (const char*)BL + (size_t)(n0 + row) * 1024 + kk * 64 + ch * 16;
        CP_ASYNC16(s_stage + buf * 8192 + sw8(row, ch), src);
    }
    CP_COMMIT();
}

template <int MODE>
__global__ void __launch_bounds__(256, 1)
mma_gibbs_kernel(const int8_t* __restrict__ A,
                 const int8_t* __restrict__ BH,
                 const int8_t* __restrict__ BL,
                 const float* __restrict__ bias,
                 int8_t* __restrict__ Out,
                 float* __restrict__ fe_part,
                 uint32_t k0, uint32_t k1)
{
    extern __shared__ char smem[];
    const uint32_t sbase = smem_u32(smem);
    const int tid = threadIdx.x;
    const int wid = tid >> 5, lane = tid & 31;
    const int warp_m = wid & 1;          // 0..1 -> 64-row halves
    const int warp_n = wid >> 1;         // 0..3 -> 32-col quarters
    const int m0 = blockIdx.y * 128;
    const int n0 = blockIdx.x * 128;

    int acch[4][4][4], accl[4][4][4];    // [mt(16m)][n8][frag]
    #pragma unroll
    for (int i = 0; i < 4; i++)
        #pragma unroll
        for (int j = 0; j < 4; j++)
            #pragma unroll
            for (int q = 0; q < 4; q++) { acch[i][j][q] = 0; accl[i][j][q] = 0; }

    // Prologue: pre-issue 3 stages
    stage_load(sbase + 0 * STAGE_BYTES, A, BH, BL, m0, n0, 0, tid);
    stage_load(sbase + 1 * STAGE_BYTES, A, BH, BL, m0, n0, 1, tid);
    stage_load(sbase + 2 * STAGE_BYTES, A, BH, BL, m0, n0, 2, tid);

    const int la = lane & 15, ha = lane >> 4;

    #pragma unroll 1
    for (int kk = 0; kk < NKIT; kk++) {
        if (kk <= NKIT - 3)      CP_WAIT2();
        else if (kk == NKIT - 2) CP_WAIT1();
        else                     CP_WAIT0();
        __syncthreads();
        if (kk + 3 < NKIT)
            stage_load(sbase + (uint32_t)((kk + 3) & 3) * STAGE_BYTES, A, BH, BL, m0, n0, kk + 3, tid);

        const uint32_t s = sbase + (uint32_t)(kk & 3) * STAGE_BYTES;
        #pragma unroll
        for (int ks = 0; ks < 2; ks++) {
            const int c = ks * 2 + ha;   // 16B chunk index within 64B row
            uint32_t a[4][4];
            #pragma unroll
            for (int mt = 0; mt < 4; mt++)
                ldsm4(a[mt], s + sw8(warp_m * 64 + mt * 16 + la, c));
            uint32_t bh[2][4], bl[2][4];
            #pragma unroll
            for (int g = 0; g < 2; g++) {
                ldsm4(bh[g], s + 8192u  + sw8(warp_n * 32 + g * 16 + la, c));
                ldsm4(bl[g], s + 16384u + sw8(warp_n * 32 + g * 16 + la, c));
            }
            #pragma unroll
            for (int mt = 0; mt < 4; mt++)
                #pragma unroll
                for (int n8 = 0; n8 < 4; n8++) {
                    imma16832(acch[mt][n8], a[mt], bh[n8 >> 1][n8 & 1], bh[n8 >> 1][(n8 & 1) + 2]);
                    imma16832(accl[mt][n8], a[mt], bl[n8 >> 1][n8 & 1], bl[n8 >> 1][(n8 & 1) + 2]);
                }
        }
    }
    __syncthreads();

    // Combine planes and spill z_int to smem (stride 132 ints)
    int* zs = (int*)smem;
    #pragma unroll
    for (int mt = 0; mt < 4; mt++)
        #pragma unroll
        for (int n8 = 0; n8 < 4; n8++) {
            int r = warp_m * 64 + mt * 16 + (lane >> 2);
            int c = warp_n * 32 + n8 * 8 + (lane & 3) * 2;
            zs[r * 132 + c]           = (acch[mt][n8][0] << 8) + accl[mt][n8][0];
            zs[r * 132 + c + 1]       = (acch[mt][n8][1] << 8) + accl[mt][n8][1];
            zs[(r + 8) * 132 + c]     = (acch[mt][n8][2] << 8) + accl[mt][n8][2];
            zs[(r + 8) * 132 + c + 1] = (acch[mt][n8][3] << 8) + accl[mt][n8][3];
        }
    __syncthreads();

    // Per-thread epilogue: row = tid>>1 (local), 64-col half = tid&1
    const float inv_s = g_inv_scale;
    const int rloc = tid >> 1;
    const int c0 = (tid & 1) * 64;
    const int row = m0 + rloc;
    const int* zrow = zs + rloc * 132 + c0;
    const float4* bp = (const float4*)(bias + (size_t)row * 1024 + n0 + c0);

    if (MODE == 0) {
        const uint32_t ibase = (uint32_t)(row * 1024 + n0 + c0);
        uint4* op = (uint4*)(Out + (size_t)row * 1024 + n0 + c0);
        #pragma unroll 1
        for (int j0 = 0; j0 < 64; j0 += 16) {
            uint32_t pk[4];
            #pragma unroll
            for (int q4 = 0; q4 < 4; q4++) {
                float4 bv = bp[j0 / 4 + q4];
                float zb[4] = {bv.x, bv.y, bv.z, bv.w};
                uint32_t bytes = 0;
                #pragma unroll
                for (int jj = 0; jj < 4; jj++) {
                    int j = j0 + q4 * 4 + jj;
                    float z = (float)zrow[j] * inv_s + zb[jj];
                    float e = __expf(-z);
                    float u = urand(k0, k1, ibase + (uint32_t)j);
                    bytes |= (fmaf(u, e, u) < 1.0f ? 1u : 0u) << (jj * 8);
                }
                pk[q4] = bytes;
            }
            op[j0 / 16] = make_uint4(pk[0], pk[1], pk[2], pk[3]);
        }
    } else {
        float sp_acc = 0.0f;
        #pragma unroll 1
        for (int j0 = 0; j0 < 64; j0 += 8) {
            float4 bv0 = bp[j0 / 4], bv1 = bp[j0 / 4 + 1];
            float zb[8] = {bv0.x, bv0.y, bv0.z, bv0.w, bv1.x, bv1.y, bv1.z, bv1.w};
            #pragma unroll
            for (int jj = 0; jj < 8; jj++) {
                float z = (float)zrow[j0 + jj] * inv_s + zb[jj];
                sp_acc += fmaxf(z, 0.0f) + log1pf(expf(-fabsf(z)));
            }
        }
        fe_part[(size_t)row * 16 + blockIdx.x * 2 + (tid & 1)] = sp_acc;
    }
}

// ---------------------------------------------------------------------------
// fe[row] = -(v . bmod_row) - sum(fe_part[row, :16])
// ---------------------------------------------------------------------------
__global__ void rowdot_kernel(const int8_t* __restrict__ v, const float* __restrict__ bmod,
                              const float* __restrict__ part, float* __restrict__ fe)
{
    int row = blockIdx.x;
    int tid = threadIdx.x;  // 256
    float s = 0.0f;
    for (int q = tid; q < NV; q += 256)
        s += (float)v[(size_t)row * NV + q] * bmod[(size_t)row * NV + q];
    __shared__ float red[8];
    #pragma unroll
    for (int off = 16; off; off >>= 1) s += __shfl_down_sync(0xffffffffu, s, off);
    if ((tid & 31) == 0) red[tid >> 5] = s;
    __syncthreads();
    if (tid == 0) {
        float dsum = 0.0f;
        #pragma unroll
        for (int w = 0; w < 8; w++) dsum += red[w];
        float sp = 0.0f;
        #pragma unroll
        for (int j = 0; j < 16; j++) sp += part[(size_t)row * 16 + j];
        fe[row] = -dsum - sp;
    }
}

__global__ void final_kernel(float* __restrict__ out)
{
    int tid = threadIdx.x;  // 256
    double s = 0.0;
    for (int i = tid; i < NB; i += 256)
        s += (double)g_fe_d[i] - (double)g_fe_m[i];
    __shared__ double red[8];
    #pragma unroll
    for (int off = 16; off; off >>= 1) s += __shfl_down_sync(0xffffffffu, s, off);
    if ((tid & 31) == 0) red[tid >> 5] = s;
    __syncthreads();
    if (tid == 0) {
        double t = 0.0;
        #pragma unroll
        for (int w = 0; w < 8; w++) t += red[w];
        out[0] = (float)(t / (double)NB);
    }
}

// ---------------------------------------------------------------------------
// Host orchestration
// ---------------------------------------------------------------------------
static void host_split_keys(uint32_t& sk0, uint32_t& sk1,
                            uint32_t* kh0, uint32_t* kh1,
                            uint32_t* kv0, uint32_t* kv1)
{
    uint32_t rk0 = 0u, rk1 = 42u;
    uint32_t ck0, ck1;
    threefry(rk0, rk1, 0u, 0u, ck0, ck1);  // k_chain
    threefry(rk0, rk1, 0u, 1u, sk0, sk1);  // k_start
    uint32_t k0 = ck0, k1 = ck1;
    for (int s = 0; s < NSTEPS; s++) {
        uint32_t nk0, nk1;
        threefry(k0, k1, 0u, 0u, nk0, nk1);
        threefry(k0, k1, 0u, 1u, kh0[s], kh1[s]);
        threefry(k0, k1, 0u, 2u, kv0[s], kv1[s]);
        k0 = nk0; k1 = nk1;
    }
}

extern "C" void kernel_launch(void* const* d_in, const int* in_sizes, int n_in,
                              void* d_out, int out_size)
{
    const float* v_data = (const float*)d_in[0];
    const float* cond   = (const float*)d_in[1];
    const float* W      = (const float*)d_in[2];
    const float* b      = (const float*)d_in[3];
    const float* c      = (const float*)d_in[4];
    const float* W1     = (const float*)d_in[5];
    const float* b1     = (const float*)d_in[6];
    const float* W2     = (const float*)d_in[7];
    const float* b2     = (const float*)d_in[8];
    float* out = (float*)d_out;

    uint32_t sk0, sk1;
    uint32_t kh0[NSTEPS], kh1[NSTEPS], kv0[NSTEPS], kv1[NSTEPS];
    host_split_keys(sk0, sk1, kh0, kh1, kv0, kv1);

    cudaFuncSetAttribute(mma_gibbs_kernel<0>, cudaFuncAttributeMaxDynamicSharedMemorySize, SMEM_TOTAL);
    cudaFuncSetAttribute(mma_gibbs_kernel<1>, cudaFuncAttributeMaxDynamicSharedMemorySize, SMEM_TOTAL);

    int8_t *p_v, *p_h, *p_vd, *p_Whi, *p_Wlo, *p_WThi, *p_WTlo;
    float *p_bmod, *p_cmod, *p_fed, *p_fem, *p_fpd, *p_fpm;
    cudaGetSymbolAddress((void**)&p_v, g_v);
    cudaGetSymbolAddress((void**)&p_h, g_h);
    cudaGetSymbolAddress((void**)&p_vd, g_vd);
    cudaGetSymbolAddress((void**)&p_Whi, g_Whi);
    cudaGetSymbolAddress((void**)&p_Wlo, g_Wlo);
    cudaGetSymbolAddress((void**)&p_WThi, g_WThi);
    cudaGetSymbolAddress((void**)&p_WTlo, g_WTlo);
    cudaGetSymbolAddress((void**)&p_bmod, g_bmod);
    cudaGetSymbolAddress((void**)&p_cmod, g_cmod);
    cudaGetSymbolAddress((void**)&p_fed, g_fe_d);
    cudaGetSymbolAddress((void**)&p_fem, g_fe_m);
    cudaGetSymbolAddress((void**)&p_fpd, g_fep_d);
    cudaGetSymbolAddress((void**)&p_fpm, g_fep_m);

    wmax_reset_kernel<<<1, 1>>>();
    wmax_kernel<<<(NV * NH) / 1024, 256>>>(W);
    quant_kernel<<<dim3(32, 32), dim3(32, 8)>>>(W);
    params_kernel<<<NB / PROWS, 256>>>(cond, b, c, W1, b1, W2, b2);
    init_v_kernel<<<(NB * NV) / 256, 256>>>(sk0, sk1);
    conv_vdata_kernel<<<(NB * NV) / 256, 256>>>(v_data);

    dim3 ggrid(8, 128);
    for (int s = 0; s < NSTEPS; s++) {
        // h = bern(sigmoid(v @ W + c_mod)); B planes = W^T hi/lo
        mma_gibbs_kernel<0><<<ggrid, 256, SMEM_TOTAL>>>(
            p_v, p_WThi, p_WTlo, p_cmod, p_h, nullptr, kh0[s], kh1[s]);
        // v = bern(sigmoid(h @ W^T + b_mod)); B planes = W hi/lo
        mma_gibbs_kernel<0><<<ggrid, 256, SMEM_TOTAL>>>(
            p_h, p_Whi, p_Wlo, p_bmod, p_v, nullptr, kv0[s], kv1[s]);
    }
    // free-energy softplus partials
    mma_gibbs_kernel<1><<<ggrid, 256, SMEM_TOTAL>>>(
        p_vd, p_WThi, p_WTlo, p_cmod, nullptr, p_fpd, 0u, 0u);
    mma_gibbs_kernel<1><<<ggrid, 256, SMEM_TOTAL>>>(
        p_v, p_WThi, p_WTlo, p_cmod, nullptr, p_fpm, 0u, 0u);
    rowdot_kernel<<<NB, 256>>>(p_vd, p_bmod, p_fpd, p_fed);
    rowdot_kernel<<<NB, 256>>>(p_v, p_bmod, p_fpm, p_fem);
    final_kernel<<<1, 256>>>(out);
}

// round 6
// speedup vs baseline: 3.8289x; 3.8289x over previous
#include <cuda_runtime.h>
#include <cuda_bf16.h>
#include <cuda_fp16.h>
#include <cstdint>

#define NB 16384
#define NV 1024
#define NH 1024
#define NC 64
#define NSTEPS 25

// ---------------------------------------------------------------------------
// Scratch (static __device__ allocations; no cudaMalloc anywhere)
// ---------------------------------------------------------------------------
__device__ float g_bmod[NB * NV];               // 64 MB
__device__ float g_cmod[NB * NH];               // 64 MB
__device__ __half g_v[NB * NV];                 // 32 MB (current v, 0/1 fp16)
__device__ __half g_h[NB * NH];                 // 32 MB
__device__ __nv_bfloat16 g_v_bf[NB * NV];       // 32 MB (v_model as bf16, for FE)
__device__ __nv_bfloat16 g_vd_bf[NB * NV];      // 32 MB (v_data as bf16, for FE)
__device__ __half g_Wh[NV * NH];                // W fp16 [V][H]   (chain v-step B)
__device__ __half g_WTh[NH * NV];               // W^T fp16 [H][V] (chain h-step B)
__device__ __nv_bfloat16 g_WTb1[NH * NV];       // W^T bf16 hi split (FE)
__device__ __nv_bfloat16 g_WTb2[NH * NV];       // W^T bf16 lo split (FE)
__device__ float g_fe_d[NB];
__device__ float g_fe_m[NB];
__device__ float g_fep_d[NB * 16];              // per-(row, 64-col block) softplus partials
__device__ float g_fep_m[NB * 16];

// ---------------------------------------------------------------------------
// threefry2x32 (exact JAX semantics, jax_threefry_partitionable)
// ---------------------------------------------------------------------------
__host__ __device__ __forceinline__ void threefry(uint32_t k0, uint32_t k1,
                                                  uint32_t x0, uint32_t x1,
                                                  uint32_t& o0, uint32_t& o1)
{
    uint32_t ks2 = k0 ^ k1 ^ 0x1BD11BDAu;
#define TF_ROT(x, r) (((x) << (r)) | ((x) >> (32 - (r))))
#define TF_RND(r) { x0 += x1; x1 = TF_ROT(x1, r); x1 ^= x0; }
    x0 += k0; x1 += k1;
    TF_RND(13) TF_RND(15) TF_RND(26) TF_RND(6)
    x0 += k1; x1 += ks2 + 1u;
    TF_RND(17) TF_RND(29) TF_RND(16) TF_RND(24)
    x0 += ks2; x1 += k0 + 2u;
    TF_RND(13) TF_RND(15) TF_RND(26) TF_RND(6)
    x0 += k0; x1 += k1 + 3u;
    TF_RND(17) TF_RND(29) TF_RND(16) TF_RND(24)
    x0 += k1; x1 += ks2 + 4u;
    TF_RND(13) TF_RND(15) TF_RND(26) TF_RND(6)
    x0 += ks2; x1 += k0 + 5u;
    o0 = x0; o1 = x1;
#undef TF_RND
#undef TF_ROT
}

__device__ __forceinline__ float urand(uint32_t k0, uint32_t k1, uint32_t idx)
{
    uint32_t a, b;
    threefry(k0, k1, 0u, idx, a, b);
    uint32_t bits = a ^ b;
    return __uint_as_float((bits >> 9) | 0x3F800000u) - 1.0f;
}

// ---------------------------------------------------------------------------
// MMA / ldmatrix / cp.async helpers (baseline PTX, legal on plain sm_103)
// ---------------------------------------------------------------------------
__device__ __forceinline__ uint32_t smem_u32(const void* p) {
    uint32_t a;
    asm("{ .reg .u64 t; cvta.to.shared.u64 t, %1; cvt.u32.u64 %0, t; }" : "=r"(a) : "l"(p));
    return a;
}
__device__ __forceinline__ void ldsm4(uint32_t* r, uint32_t addr) {
    asm volatile("ldmatrix.sync.aligned.m8n8.x4.shared.b16 {%0,%1,%2,%3}, [%4];"
                 : "=r"(r[0]), "=r"(r[1]), "=r"(r[2]), "=r"(r[3]) : "r"(addr));
}
__device__ __forceinline__ void mma_bf16(float* d, const uint32_t* a, uint32_t b0, uint32_t b1) {
    asm volatile("mma.sync.aligned.m16n8k16.row.col.f32.bf16.bf16.f32 "
                 "{%0,%1,%2,%3}, {%4,%5,%6,%7}, {%8,%9}, {%0,%1,%2,%3};"
                 : "+f"(d[0]), "+f"(d[1]), "+f"(d[2]), "+f"(d[3])
                 : "r"(a[0]), "r"(a[1]), "r"(a[2]), "r"(a[3]), "r"(b0), "r"(b1));
}
__device__ __forceinline__ void mma_f16(float* d, const uint32_t* a, uint32_t b0, uint32_t b1) {
    asm volatile("mma.sync.aligned.m16n8k16.row.col.f32.f16.f16.f32 "
                 "{%0,%1,%2,%3}, {%4,%5,%6,%7}, {%8,%9}, {%0,%1,%2,%3};"
                 : "+f"(d[0]), "+f"(d[1]), "+f"(d[2]), "+f"(d[3])
                 : "r"(a[0]), "r"(a[1]), "r"(a[2]), "r"(a[3]), "r"(b0), "r"(b1));
}
#define CP_ASYNC16(dst, src) \
    asm volatile("cp.async.cg.shared.global [%0], [%1], 16;" :: "r"(dst), "l"(src))
#define CP_COMMIT() asm volatile("cp.async.commit_group;")
#define CP_WAIT1()  asm volatile("cp.async.wait_group 1;")
#define CP_WAIT0()  asm volatile("cp.async.wait_group 0;")

__device__ __forceinline__ uint32_t swz(uint32_t off) {  // SW128 on 128B rows
    return off ^ ((off >> 3) & 0x70);
}

// ---------------------------------------------------------------------------
// W -> fp16 plane (both orientations) + bf16 2-way split of W^T (for FE)
// ---------------------------------------------------------------------------
__global__ void split_kernel(const float* __restrict__ W)
{
    __shared__ __half tf[32][33];
    __shared__ __nv_bfloat16 t1[32][33], t2[32][33];
    int bx = blockIdx.x * 32;   // h
    int by = blockIdx.y * 32;   // v
    int tx = threadIdx.x, ty = threadIdx.y;  // 32 x 8
    #pragma unroll
    for (int i = 0; i < 32; i += 8) {
        float w = W[(size_t)(by + ty + i) * NH + bx + tx];
        __half hf = __float2half(w);
        __nv_bfloat16 h1 = __float2bfloat16(w);
        float r = w - __bfloat162float(h1);
        __nv_bfloat16 h2 = __float2bfloat16(r);
        size_t o = (size_t)(by + ty + i) * NH + bx + tx;
        g_Wh[o] = hf;
        tf[ty + i][tx] = hf; t1[ty + i][tx] = h1; t2[ty + i][tx] = h2;
    }
    __syncthreads();
    #pragma unroll
    for (int i = 0; i < 32; i += 8) {
        size_t o = (size_t)(bx + ty + i) * NV + by + tx;
        g_WTh[o]  = tf[tx][ty + i];
        g_WTb1[o] = t1[tx][ty + i];
        g_WTb2[o] = t2[tx][ty + i];
    }
}

// ---------------------------------------------------------------------------
// Conditioning MLP -> b_mod, c_mod
// ---------------------------------------------------------------------------
#define PROWS 8
__global__ void params_kernel(const float* __restrict__ cond, const float* __restrict__ b,
                              const float* __restrict__ c, const float* __restrict__ W1,
                              const float* __restrict__ b1, const float* __restrict__ W2,
                              const float* __restrict__ b2)
{
    __shared__ float sc[PROWS][NC];
    __shared__ float st[PROWS][NC];
    int row0 = blockIdx.x * PROWS;
    int tid = threadIdx.x;  // 256

    for (int i = tid; i < PROWS * NC; i += 256)
        sc[i / NC][i % NC] = cond[(size_t)(row0 + i / NC) * NC + (i % NC)];
    __syncthreads();
    for (int i = tid; i < PROWS * NC; i += 256) {
        int r = i / NC, j = i % NC;
        float s = b1[j];
        #pragma unroll 8
        for (int k = 0; k < NC; k++) s += sc[r][k] * W1[k * NC + j];
        st[r][j] = tanhf(s);
    }
    __syncthreads();

    for (int q = tid; q < NV; q += 256) {
        float ga[PROWS], be[PROWS];
        float ig = b2[q], ib = b2[NV + q];
        #pragma unroll
        for (int r = 0; r < PROWS; r++) { ga[r] = ig; be[r] = ib; }
        for (int k = 0; k < NC; k++) {
            float wg = W2[(size_t)k * 4096 + q];
            float wb = W2[(size_t)k * 4096 + NV + q];
            #pragma unroll
            for (int r = 0; r < PROWS; r++) { ga[r] += st[r][k] * wg; be[r] += st[r][k] * wb; }
        }
        float bq = b[q];
        #pragma unroll
        for (int r = 0; r < PROWS; r++)
            g_bmod[(size_t)(row0 + r) * NV + q] = (1.0f + ga[r]) * bq + be[r];
    }
    for (int q = tid; q < NH; q += 256) {
        float ga[PROWS], be[PROWS];
        float ig = b2[2 * NV + q], ib = b2[2 * NV + NH + q];
        #pragma unroll
        for (int r = 0; r < PROWS; r++) { ga[r] = ig; be[r] = ib; }
        for (int k = 0; k < NC; k++) {
            float wg = W2[(size_t)k * 4096 + 2 * NV + q];
            float wb = W2[(size_t)k * 4096 + 2 * NV + NH + q];
            #pragma unroll
            for (int r = 0; r < PROWS; r++) { ga[r] += st[r][k] * wg; be[r] += st[r][k] * wb; }
        }
        float cq = c[q];
        #pragma unroll
        for (int r = 0; r < PROWS; r++)
            g_cmod[(size_t)(row0 + r) * NH + q] = (1.0f + ga[r]) * cq + be[r];
    }
}

// ---------------------------------------------------------------------------
// init / conversion kernels
// ---------------------------------------------------------------------------
__global__ void init_v_kernel(uint32_t k0, uint32_t k1)
{
    uint32_t i = blockIdx.x * blockDim.x + threadIdx.x;
    float u = urand(k0, k1, i);
    ((uint16_t*)g_v)[i] = (u < 0.5f) ? 0x3C00u : 0u;   // fp16 1.0 / 0.0
}
__global__ void conv_vdata_kernel(const float* __restrict__ vd)
{
    uint32_t i = blockIdx.x * blockDim.x + threadIdx.x;
    g_vd_bf[i] = __float2bfloat16(vd[i]);
}
__global__ void conv_vmodel_kernel()
{
    uint32_t i = blockIdx.x * blockDim.x + threadIdx.x;
    // v is exactly 0.0 or 1.0 in fp16
    g_v_bf[i] = (((const uint16_t*)g_v)[i] == 0x3C00u) ? __float2bfloat16(1.0f)
                                                       : __float2bfloat16(0.0f);
}

// ---------------------------------------------------------------------------
// mma.sync fused GEMM: Z[128x128 tile] = A @ (sum of NSPLIT B planes)^T + bias
//   NSPLIT=1: fp16 operands (chain).  NSPLIT=2: bf16 hi/lo splits (FE).
//   MODE 0: Out(half) = bernoulli(sigmoid(Z))
//   MODE 1: fe_part[row*16 + bx*2 + half] = sum_{64 cols} softplus(Z)
// 2-stage cp.async pipeline, K-chunk 64, warps 2(M)x4(N), warp tile 64x32.
// ---------------------------------------------------------------------------
#define ZSPILL_BYTES (128 * 132 * 4)   // 67584

template <int NSPLIT>
__device__ __forceinline__ void stage_load(uint32_t s_stage,
    const uint16_t* A, const uint16_t* B1, const uint16_t* B2,
    int m0, int n0, int kk, int tid)
{
    #pragma unroll
    for (int r = 0; r < 4 * (1 + NSPLIT); r++) {
        int i = tid + r * 256;          // chunk id
        int buf = i >> 10;              // 0:A 1:B1 [2:B2]
        int row = (i >> 3) & 127;
        int ch  = i & 7;
        const char* src;
        if (buf == 0)      src = (const char*)A  + (size_t)(m0 + row) * 2048 + kk * 128 + ch * 16;
        else if (buf == 1) src = (const char*)B1 + (size_t)(n0 + row) * 2048 + kk * 128 + ch * 16;
        else               src = (const char*)B2 + (size_t)(n0 + row) * 2048 + kk * 128 + ch * 16;
        uint32_t off = (uint32_t)(row * 128 + ch * 16);
        CP_ASYNC16(s_stage + buf * 16384 + swz(off), src);
    }
    CP_COMMIT();
}

template <int MODE, int NSPLIT>
__global__ void __launch_bounds__(256, 2)
mma_gibbs_kernel(const uint16_t* __restrict__ A,
                 const uint16_t* __restrict__ B1,
                 const uint16_t* __restrict__ B2,
                 const float* __restrict__ bias,
                 __half* __restrict__ Out,
                 float* __restrict__ fe_part,
                 uint32_t k0, uint32_t k1)
{
    constexpr uint32_t STG = 16384u * (1 + NSPLIT);
    extern __shared__ char smem[];
    const uint32_t sbase = smem_u32(smem);
    const int tid = threadIdx.x;
    const int wid = tid >> 5, lane = tid & 31;
    const int warp_m = wid & 1;          // 0..1 -> 64-row halves
    const int warp_n = wid >> 1;         // 0..3 -> 32-col quarters
    const int m0 = blockIdx.y * 128;
    const int n0 = blockIdx.x * 128;

    float acc[4][4][4];                  // [mt(16m)][n8][frag]
    #pragma unroll
    for (int i = 0; i < 4; i++)
        #pragma unroll
        for (int j = 0; j < 4; j++)
            #pragma unroll
            for (int q = 0; q < 4; q++) acc[i][j][q] = 0.0f;

    stage_load<NSPLIT>(sbase, A, B1, B2, m0, n0, 0, tid);

    const int la = lane & 15, ha = lane >> 4;

    #pragma unroll 1
    for (int kk = 0; kk < 16; kk++) {
        const uint32_t s = sbase + (uint32_t)(kk & 1) * STG;
        if (kk + 1 < 16) {
            stage_load<NSPLIT>(sbase + (uint32_t)((kk + 1) & 1) * STG, A, B1, B2, m0, n0, kk + 1, tid);
            CP_WAIT1();
        } else {
            CP_WAIT0();
        }
        __syncthreads();

        #pragma unroll
        for (int ks = 0; ks < 4; ks++) {
            uint32_t a[4][4];
            #pragma unroll
            for (int mt = 0; mt < 4; mt++) {
                uint32_t off = (uint32_t)((warp_m * 64 + mt * 16 + la) * 128 + ks * 32 + ha * 16);
                ldsm4(a[mt], s + swz(off));
            }
            #pragma unroll
            for (int sp = 0; sp < NSPLIT; sp++) {
                uint32_t b[2][4];
                #pragma unroll
                for (int g = 0; g < 2; g++) {
                    uint32_t off = (uint32_t)((warp_n * 32 + g * 16 + la) * 128 + ks * 32 + ha * 16);
                    ldsm4(b[g], s + 16384u * (1 + sp) + swz(off));
                }
                #pragma unroll
                for (int mt = 0; mt < 4; mt++)
                    #pragma unroll
                    for (int n8 = 0; n8 < 4; n8++) {
                        if (NSPLIT == 1)
                            mma_f16(acc[mt][n8], a[mt], b[n8 >> 1][n8 & 1], b[n8 >> 1][(n8 & 1) + 2]);
                        else
                            mma_bf16(acc[mt][n8], a[mt], b[n8 >> 1][n8 & 1], b[n8 >> 1][(n8 & 1) + 2]);
                    }
            }
        }
        __syncthreads();
    }

    // Spill Z to smem (stride 132 floats to dodge bank conflicts)
    float* zs = (float*)smem;
    #pragma unroll
    for (int mt = 0; mt < 4; mt++)
        #pragma unroll
        for (int n8 = 0; n8 < 4; n8++) {
            int r = warp_m * 64 + mt * 16 + (lane >> 2);
            int c = warp_n * 32 + n8 * 8 + (lane & 3) * 2;
            zs[r * 132 + c]           = acc[mt][n8][0];
            zs[r * 132 + c + 1]       = acc[mt][n8][1];
            zs[(r + 8) * 132 + c]     = acc[mt][n8][2];
            zs[(r + 8) * 132 + c + 1] = acc[mt][n8][3];
        }
    __syncthreads();

    // Per-thread epilogue: row = tid>>1 (local), 64-col half = tid&1
    const int rloc = tid >> 1;
    const int c0 = (tid & 1) * 64;
    const int row = m0 + rloc;
    const float* zrow = zs + rloc * 132 + c0;
    const float4* bp = (const float4*)(bias + (size_t)row * 1024 + n0 + c0);

    if (MODE == 0) {
        const uint32_t ibase = (uint32_t)(row * 1024 + n0 + c0);
        uint4* op = (uint4*)(Out + (size_t)row * 1024 + n0 + c0);
        #pragma unroll 1
        for (int j0 = 0; j0 < 64; j0 += 8) {
            float4 bv0 = bp[j0 / 4], bv1 = bp[j0 / 4 + 1];
            float zb[8] = {bv0.x, bv0.y, bv0.z, bv0.w, bv1.x, bv1.y, bv1.z, bv1.w};
            uint32_t pk[4];
            #pragma unroll
            for (int jj = 0; jj < 8; jj += 2) {
                float z0 = zrow[j0 + jj] + zb[jj];
                float z1 = zrow[j0 + jj + 1] + zb[jj + 1];
                float e0 = __expf(-z0), e1 = __expf(-z1);
                float u0 = urand(k0, k1, ibase + (uint32_t)(j0 + jj));
                float u1 = urand(k0, k1, ibase + (uint32_t)(j0 + jj) + 1u);
                uint32_t s0 = (fmaf(u0, e0, u0) < 1.0f) ? 0x3C00u : 0u;  // fp16 1.0
                uint32_t s1 = (fmaf(u1, e1, u1) < 1.0f) ? 0x3C00u : 0u;
                pk[jj >> 1] = s0 | (s1 << 16);
            }
            op[j0 / 8] = make_uint4(pk[0], pk[1], pk[2], pk[3]);
        }
    } else {
        float sp_acc = 0.0f;
        #pragma unroll 1
        for (int j0 = 0; j0 < 64; j0 += 8) {
            float4 bv0 = bp[j0 / 4], bv1 = bp[j0 / 4 + 1];
            float zb[8] = {bv0.x, bv0.y, bv0.z, bv0.w, bv1.x, bv1.y, bv1.z, bv1.w};
            #pragma unroll
            for (int jj = 0; jj < 8; jj++) {
                float z = zrow[j0 + jj] + zb[jj];
                sp_acc += fmaxf(z, 0.0f) + log1pf(expf(-fabsf(z)));
            }
        }
        fe_part[(size_t)row * 16 + blockIdx.x * 2 + (tid & 1)] = sp_acc;
    }
}

// ---------------------------------------------------------------------------
// fe[row] = -(v . bmod_row) - sum(fe_part[row, :16])   (bf16 v variant)
// ---------------------------------------------------------------------------
__global__ void rowdot_kernel(const __nv_bfloat16* __restrict__ v, const float* __restrict__ bmod,
                              const float* __restrict__ part, float* __restrict__ fe)
{
    int row = blockIdx.x;
    int tid = threadIdx.x;  // 256
    float s = 0.0f;
    for (int q = tid; q < NV; q += 256)
        s += __bfloat162float(v[(size_t)row * NV + q]) * bmod[(size_t)row * NV + q];
    __shared__ float red[8];
    #pragma unroll
    for (int off = 16; off; off >>= 1) s += __shfl_down_sync(0xffffffffu, s, off);
    if ((tid & 31) == 0) red[tid >> 5] = s;
    __syncthreads();
    if (tid == 0) {
        float dsum = 0.0f;
        #pragma unroll
        for (int w = 0; w < 8; w++) dsum += red[w];
        float sp = 0.0f;
        #pragma unroll
        for (int j = 0; j < 16; j++) sp += part[(size_t)row * 16 + j];
        fe[row] = -dsum - sp;
    }
}

__global__ void final_kernel(float* __restrict__ out)
{
    int tid = threadIdx.x;  // 256
    double s = 0.0;
    for (int i = tid; i < NB; i += 256)
        s += (double)g_fe_d[i] - (double)g_fe_m[i];
    __shared__ double red[8];
    #pragma unroll
    for (int off = 16; off; off >>= 1) s += __shfl_down_sync(0xffffffffu, s, off);
    if ((tid & 31) == 0) red[tid >> 5] = s;
    __syncthreads();
    if (tid == 0) {
        double t = 0.0;
        #pragma unroll
        for (int w = 0; w < 8; w++) t += red[w];
        out[0] = (float)(t / (double)NB);
    }
}

// ---------------------------------------------------------------------------
// Host orchestration
// ---------------------------------------------------------------------------
static void host_split_keys(uint32_t& sk0, uint32_t& sk1,
                            uint32_t* kh0, uint32_t* kh1,
                            uint32_t* kv0, uint32_t* kv1)
{
    uint32_t rk0 = 0u, rk1 = 42u;
    uint32_t ck0, ck1;
    threefry(rk0, rk1, 0u, 0u, ck0, ck1);  // k_chain
    threefry(rk0, rk1, 0u, 1u, sk0, sk1);  // k_start
    uint32_t k0 = ck0, k1 = ck1;
    for (int s = 0; s < NSTEPS; s++) {
        uint32_t nk0, nk1;
        threefry(k0, k1, 0u, 0u, nk0, nk1);
        threefry(k0, k1, 0u, 1u, kh0[s], kh1[s]);
        threefry(k0, k1, 0u, 2u, kv0[s], kv1[s]);
        k0 = nk0; k1 = nk1;
    }
}

extern "C" void kernel_launch(void* const* d_in, const int* in_sizes, int n_in,
                              void* d_out, int out_size)
{
    const float* v_data = (const float*)d_in[0];
    const float* cond   = (const float*)d_in[1];
    const float* W      = (const float*)d_in[2];
    const float* b      = (const float*)d_in[3];
    const float* c      = (const float*)d_in[4];
    const float* W1     = (const float*)d_in[5];
    const float* b1     = (const float*)d_in[6];
    const float* W2     = (const float*)d_in[7];
    const float* b2     = (const float*)d_in[8];
    float* out = (float*)d_out;

    uint32_t sk0, sk1;
    uint32_t kh0[NSTEPS], kh1[NSTEPS], kv0[NSTEPS], kv1[NSTEPS];
    host_split_keys(sk0, sk1, kh0, kh1, kv0, kv1);

    // smem sizes: chain = max(2 stages x 32KB, z-spill) ; FE = 2 stages x 48KB
    const int SMEM_CHAIN = (2 * 32768 > ZSPILL_BYTES) ? 2 * 32768 : ZSPILL_BYTES;  // 67584
    const int SMEM_FE    = 2 * 49152;                                              // 98304
    cudaFuncSetAttribute(mma_gibbs_kernel<0, 1>, cudaFuncAttributeMaxDynamicSharedMemorySize, SMEM_CHAIN);
    cudaFuncSetAttribute(mma_gibbs_kernel<1, 2>, cudaFuncAttributeMaxDynamicSharedMemorySize, SMEM_FE);

    uint16_t *p_v, *p_h, *p_Wh, *p_WTh, *p_WTb1, *p_WTb2, *p_vbf, *p_vdbf;
    float *p_bmod, *p_cmod, *p_fed, *p_fem, *p_fpd, *p_fpm;
    cudaGetSymbolAddress((void**)&p_v, g_v);
    cudaGetSymbolAddress((void**)&p_h, g_h);
    cudaGetSymbolAddress((void**)&p_vbf, g_v_bf);
    cudaGetSymbolAddress((void**)&p_vdbf, g_vd_bf);
    cudaGetSymbolAddress((void**)&p_Wh, g_Wh);
    cudaGetSymbolAddress((void**)&p_WTh, g_WTh);
    cudaGetSymbolAddress((void**)&p_WTb1, g_WTb1);
    cudaGetSymbolAddress((void**)&p_WTb2, g_WTb2);
    cudaGetSymbolAddress((void**)&p_bmod, g_bmod);
    cudaGetSymbolAddress((void**)&p_cmod, g_cmod);
    cudaGetSymbolAddress((void**)&p_fed, g_fe_d);
    cudaGetSymbolAddress((void**)&p_fem, g_fe_m);
    cudaGetSymbolAddress((void**)&p_fpd, g_fep_d);
    cudaGetSymbolAddress((void**)&p_fpm, g_fep_m);

    split_kernel<<<dim3(32, 32), dim3(32, 8)>>>(W);
    params_kernel<<<NB / PROWS, 256>>>(cond, b, c, W1, b1, W2, b2);
    init_v_kernel<<<(NB * NV) / 256, 256>>>(sk0, sk1);
    conv_vdata_kernel<<<(NB * NV) / 256, 256>>>(v_data);

    dim3 ggrid(8, 128);
    for (int s = 0; s < NSTEPS; s++) {
        // h = bern(sigmoid(v @ W + c_mod)); B = W^T fp16
        mma_gibbs_kernel<0, 1><<<ggrid, 256, SMEM_CHAIN>>>(
            p_v, p_WTh, nullptr, p_cmod, (__half*)p_h, nullptr, kh0[s], kh1[s]);
        // v = bern(sigmoid(h @ W^T + b_mod)); B = W fp16
        mma_gibbs_kernel<0, 1><<<ggrid, 256, SMEM_CHAIN>>>(
            p_h, p_Wh, nullptr, p_bmod, (__half*)p_v, nullptr, kv0[s], kv1[s]);
    }
    // v_model (fp16) -> bf16 for FE
    conv_vmodel_kernel<<<(NB * NV) / 256, 256>>>();
    // free-energy softplus partials (bf16 2-split, high precision)
    mma_gibbs_kernel<1, 2><<<ggrid, 256, SMEM_FE>>>(
        p_vdbf, p_WTb1, p_WTb2, p_cmod, nullptr, p_fpd, 0u, 0u);
    mma_gibbs_kernel<1, 2><<<ggrid, 256, SMEM_FE>>>(
        p_vbf, p_WTb1, p_WTb2, p_cmod, nullptr, p_fpm, 0u, 0u);
    rowdot_kernel<<<NB, 256>>>((const __nv_bfloat16*)p_vdbf, p_bmod, p_fpd, p_fed);
    rowdot_kernel<<<NB, 256>>>((const __nv_bfloat16*)p_vbf, p_bmod, p_fpm, p_fem);
    final_kernel<<<1, 256>>>(out);
}